// round 12
// baseline (speedup 1.0000x reference)
#include <cuda_runtime.h>
#include <cuda_fp16.h>
#include <math.h>

// ---------------- scratch (device globals; no allocation allowed) ----------
#define MAXN 50000
#define MAXE 800000
#define NG   128
#define INF_ 128
#define HID  64
#define OUTF 32

__device__ unsigned long long g_degcnt[MAXN];  // hi32 = indeg, lo32 = ew*4096
__device__ float   g_dinv[MAXN];
__device__ __half2 g_h[(size_t)MAXN * 32];     // x @ W, fp16 storage
__device__ int     g_indeg[MAXN];
__device__ int     g_off[MAXN];
__device__ int     g_cursor[MAXN];
__device__ float2  g_csr[MAXE];                // (.x = bitcast src, .y = dinv[src]*ew)
__device__ unsigned long long g_lookback[256];
__device__ int     g_gstart[NG + 1];
__device__ float   g_sums[NG * HID];
__device__ int     g_pool_cnt[NG];
__device__ int     g_is64;

__device__ __forceinline__ int load_idx(const void* p, long long i) {
    if (g_is64) return (int)((const long long*)p)[i];
    return ((const int*)p)[i];
}

// ---------------- K0: init + dtype detect -----------------------------------
__global__ void k_prep(const int* __restrict__ ei_w, int N) {
    int i = blockIdx.x * blockDim.x + threadIdx.x;
    if (i < N)        g_degcnt[i] = 0ull;
    if (i < NG * HID) g_sums[i] = 0.0f;
    if (i < NG)       g_pool_cnt[i] = 0;
    if (i < 256)      g_lookback[i] = 0ull;
    if (blockIdx.x == 0) {
        __shared__ int any_nonzero;
        if (threadIdx.x == 0) any_nonzero = 0;
        __syncthreads();
        for (int j = threadIdx.x; j < 1024; j += blockDim.x)
            if (ei_w[2 * j + 1] != 0) atomicOr(&any_nonzero, 1);
        __syncthreads();
        if (threadIdx.x == 0) g_is64 = any_nonzero ? 0 : 1;
    }
}

// ---------------- K1 (side stream): GEMM, 1 tile (64 rows) per CTA ----------
__global__ __launch_bounds__(256) void k_gemm(const float* __restrict__ x,
                                              const float* __restrict__ W,
                                              int N) {
    __shared__ float2 xs[64][33];
    __shared__ float  Ws[32][64];
    const int t = threadIdx.x;
    const int row0 = blockIdx.x * 64;
    const int ty = t >> 4, tx = t & 15;

    unsigned long long acc[4][2];
#pragma unroll
    for (int i = 0; i < 4; i++) { acc[i][0] = 0ull; acc[i][1] = 0ull; }

#pragma unroll
    for (int ch = 0; ch < 4; ch++) {
        for (int i = t; i < 512; i += 256) {
            int k = i >> 4, c4 = i & 15;
            *(float4*)&Ws[k][c4 * 4] =
                *(const float4*)(W + (size_t)(ch * 32 + k) * HID + c4 * 4);
        }
        for (int i = t; i < 512; i += 256) {
            int r = i >> 3, k4 = i & 7;
            float4 v = make_float4(0.f, 0.f, 0.f, 0.f);
            if (row0 + r < N)
                v = *(const float4*)(x + (size_t)(row0 + r) * INF_ + ch * 32 + k4 * 4);
            xs[r][k4 * 4 + 0] = make_float2(v.x, v.x);
            xs[r][k4 * 4 + 1] = make_float2(v.y, v.y);
            xs[r][k4 * 4 + 2] = make_float2(v.z, v.z);
            xs[r][k4 * 4 + 3] = make_float2(v.w, v.w);
        }
        __syncthreads();
#pragma unroll 8
        for (int k = 0; k < 32; k++) {
            union { float4 v; unsigned long long u[2]; } w;
            w.v = *(float4*)&Ws[k][tx * 4];
#pragma unroll
            for (int i = 0; i < 4; i++) {
                unsigned long long a = *(unsigned long long*)&xs[ty * 4 + i][k];
                asm("fma.rn.f32x2 %0, %1, %2, %0;"
                    : "+l"(acc[i][0]) : "l"(a), "l"(w.u[0]));
                asm("fma.rn.f32x2 %0, %1, %2, %0;"
                    : "+l"(acc[i][1]) : "l"(a), "l"(w.u[1]));
            }
        }
        __syncthreads();
    }
#pragma unroll
    for (int i = 0; i < 4; i++) {
        int row = row0 + ty * 4 + i;
        if (row < N) {
            union { unsigned long long u; float2 f; } c0, c1;
            c0.u = acc[i][0]; c1.u = acc[i][1];
            union { __half2 h[2]; uint2 u; } pk;
            pk.h[0] = __floats2half2_rn(c0.f.x, c0.f.y);
            pk.h[1] = __floats2half2_rn(c1.f.x, c1.f.y);
            *(uint2*)&g_h[(size_t)row * 32 + tx * 2] = pk.u;
        }
    }
}

// ---------------- K2: packed deg+count histogram (x2 MLP) -------------------
__global__ void k_deg(const void* __restrict__ ei, const float* __restrict__ ew,
                      int E) {
    int tid = blockIdx.x * blockDim.x + threadIdx.x;
    int stride = gridDim.x * blockDim.x;
    int e = tid, e2 = tid + stride;
    if (e >= E) return;
    bool has2 = e2 < E;
    int d1 = load_idx(ei, (long long)E + e);
    float w1 = ew[e];
    int d2 = 0; float w2 = 0.0f;
    if (has2) { d2 = load_idx(ei, (long long)E + e2); w2 = ew[e2]; }
    unsigned long long p1 = (1ull << 32) | (unsigned)__float2int_rn(w1 * 4096.0f);
    atomicAdd(&g_degcnt[d1], p1);
    if (has2) {
        unsigned long long p2 = (1ull << 32) | (unsigned)__float2int_rn(w2 * 4096.0f);
        atomicAdd(&g_degcnt[d2], p2);
    }
}

// ---------------- K3: decoupled-lookback scan + dinv + graph bounds ---------
__global__ __launch_bounds__(256) void k_scan(const void* __restrict__ batch,
                                              int N) {
    const int bid = blockIdx.x;
    const int i = bid * 256 + threadIdx.x;
    const int lane = threadIdx.x & 31, wid = threadIdx.x >> 5;
    unsigned long long dc = (i < N) ? g_degcnt[i] : 0ull;
    int v = (int)(dc >> 32);

    int xv = v;
#pragma unroll
    for (int o = 1; o < 32; o <<= 1) {
        int y = __shfl_up_sync(0xffffffffu, xv, o);
        if (lane >= o) xv += y;
    }
    __shared__ int wsum[8];
    if (lane == 31) wsum[wid] = xv;
    __syncthreads();
    if (threadIdx.x < 32) {
        int s = (threadIdx.x < 8) ? wsum[threadIdx.x] : 0;
#pragma unroll
        for (int o = 1; o < 8; o <<= 1) {
            int y = __shfl_up_sync(0xffffffffu, s, o);
            if (lane >= o) s += y;
        }
        if (threadIdx.x < 8) wsum[threadIdx.x] = s;
    }
    __syncthreads();
    int incl = xv + (wid ? wsum[wid - 1] : 0);
    int total = wsum[7];

    __shared__ int s_excl;
    if (threadIdx.x == 0) {
        if (bid == 0) {
            atomicExch(&g_lookback[0], (2ull << 32) | (unsigned)total);
            s_excl = 0;
        } else {
            atomicExch(&g_lookback[bid], (1ull << 32) | (unsigned)total);
            int ex = 0;
            int p = bid - 1;
            while (true) {
                unsigned long long w;
                do { w = *(volatile unsigned long long*)&g_lookback[p]; }
                while ((w >> 32) == 0ull);
                if ((w >> 32) == 2ull) { ex += (int)(unsigned)w; break; }
                ex += (int)(unsigned)w;
                p--;
            }
            atomicExch(&g_lookback[bid], (2ull << 32) | (unsigned)(ex + total));
            s_excl = ex;
        }
    }
    __syncthreads();
    if (i < N) {
        int excl = s_excl + incl - v;
        g_off[i]    = excl;
        g_cursor[i] = excl;
        g_indeg[i]  = v;
        float dg = (float)(unsigned)(dc & 0xffffffffull) * (1.0f / 4096.0f);
        g_dinv[i] = rsqrtf(1.0f + dg);
        int bi = load_idx(batch, i);
        int bp = (i == 0) ? -1 : load_idx(batch, i - 1);
        for (int g = bp + 1; g <= bi; g++) g_gstart[g] = i;
        if (i == N - 1)
            for (int g = bi + 1; g <= NG; g++) g_gstart[g] = N;
    }
}

// ---------------- K4: CSR fill (x2 MLP) --------------------------------------
__global__ void k_fill(const void* __restrict__ ei, const float* __restrict__ ew,
                       int E) {
    int tid = blockIdx.x * blockDim.x + threadIdx.x;
    int stride = gridDim.x * blockDim.x;
    int e = tid, e2 = tid + stride;
    if (e >= E) return;
    bool has2 = e2 < E;
    int s1 = load_idx(ei, e);
    int d1 = load_idx(ei, (long long)E + e);
    float w1 = ew[e];
    int s2 = 0, d2 = 0; float w2 = 0.0f;
    if (has2) {
        s2 = load_idx(ei, e2);
        d2 = load_idx(ei, (long long)E + e2);
        w2 = ew[e2];
    }
    float v1 = g_dinv[s1] * w1;
    float v2 = has2 ? g_dinv[s2] * w2 : 0.0f;
    int p1 = atomicAdd(&g_cursor[d1], 1);
    int p2 = has2 ? atomicAdd(&g_cursor[d2], 1) : 0;
    g_csr[p1] = make_float2(__int_as_float(s1), v1);
    if (has2) g_csr[p2] = make_float2(__int_as_float(s2), v2);
}

// ---------------- K5: aggregate (one warp/node, 8-wide gathers) --------------
__global__ __launch_bounds__(256) void k_agg(const float* __restrict__ b,
                                             float* __restrict__ out_node,
                                             int N) {
    __shared__ float2 stage[8][32];
    const int wid = threadIdx.x >> 5, lane = threadIdx.x & 31;
    const __half2* __restrict__ h2 = (const __half2*)g_h;
    int n = blockIdx.x * 8 + wid;
    if (n >= N) return;
    int start = g_off[n];
    int deg   = g_indeg[n];
    float ax = 0.0f, ay = 0.0f;
    for (int base = 0; base < deg; base += 32) {
        int j = base + lane;
        if (j < deg) stage[wid][lane] = g_csr[start + j];
        __syncwarp();
        int m = min(32, deg - base);
        int k = 0;
        for (; k + 8 <= m; k += 8) {
            float2 cw[8];
            __half2 hv[8];
#pragma unroll
            for (int u = 0; u < 8; u++) cw[u] = stage[wid][k + u];
#pragma unroll
            for (int u = 0; u < 8; u++)
                hv[u] = h2[(size_t)__float_as_int(cw[u].x) * 32 + lane];
#pragma unroll
            for (int u = 0; u < 8; u++) {
                float2 f = __half22float2(hv[u]);
                ax += f.x * cw[u].y;
                ay += f.y * cw[u].y;
            }
        }
        for (; k + 4 <= m; k += 4) {
            float2 cw[4];
            __half2 hv[4];
#pragma unroll
            for (int u = 0; u < 4; u++) cw[u] = stage[wid][k + u];
#pragma unroll
            for (int u = 0; u < 4; u++)
                hv[u] = h2[(size_t)__float_as_int(cw[u].x) * 32 + lane];
#pragma unroll
            for (int u = 0; u < 4; u++) {
                float2 f = __half22float2(hv[u]);
                ax += f.x * cw[u].y;
                ay += f.y * cw[u].y;
            }
        }
        for (; k < m; k++) {
            float2 cw = stage[wid][k];
            float2 f = __half22float2(h2[(size_t)__float_as_int(cw.x) * 32 + lane]);
            ax += f.x * cw.y;
            ay += f.y * cw.y;
        }
        __syncwarp();
    }
    float dv = g_dinv[n];
    float2 hn = __half22float2(h2[(size_t)n * 32 + lane]);
    float vx = dv * (ax + dv * hn.x) + b[lane * 2 + 0];
    float vy = dv * (ay + dv * hn.y) + b[lane * 2 + 1];
    ((float2*)out_node)[(size_t)n * 32 + lane] = make_float2(tanhf(vx), tanhf(vy));
}

// ---------------- K6: pooled mean + linear + tanh ----------------------------
__global__ __launch_bounds__(256) void k_pool(const float* __restrict__ out_node,
                                              const float* __restrict__ W1,
                                              const float* __restrict__ b1,
                                              float* __restrict__ out_graph) {
    int g = blockIdx.x >> 2;
    int chunk = blockIdx.x & 3;
    int t = threadIdx.x;
    int lo = g_gstart[g], hi = g_gstart[g + 1];

    __shared__ float part[4][64];
    int col = t & 63, rg = t >> 6;
    float a = 0.0f;
    for (int r = lo + chunk * 4 + rg; r < hi; r += 16)
        a += out_node[(size_t)r * HID + col];
    part[rg][col] = a;
    __syncthreads();
    if (t < 64) {
        float s = part[0][t] + part[1][t] + part[2][t] + part[3][t];
        if (s != 0.0f) atomicAdd(&g_sums[g * HID + t], s);
    }
    __threadfence();
    __syncthreads();

    __shared__ int s_last;
    if (t == 0) s_last = (atomicAdd(&g_pool_cnt[g], 1) == 3) ? 1 : 0;
    __syncthreads();
    if (s_last) {
        __threadfence();
        if (t < OUTF) {
            float inv = 1.0f / fmaxf((float)(hi - lo), 1.0f);
            float sum = b1[t];
#pragma unroll 8
            for (int k = 0; k < HID; k++)
                sum += (*(volatile float*)&g_sums[g * HID + k]) * inv * W1[k * OUTF + t];
            out_graph[g * OUTF + t] = tanhf(sum);
        }
    }
}

// ---------------- static stream/event (created at load, pre-checkpoint) -----
namespace {
struct SideStream {
    cudaStream_t s;
    cudaEvent_t  eFork, eJoin;
    SideStream() {
        cudaStreamCreateWithFlags(&s, cudaStreamNonBlocking);
        cudaEventCreateWithFlags(&eFork, cudaEventDisableTiming);
        cudaEventCreateWithFlags(&eJoin, cudaEventDisableTiming);
    }
};
SideStream g_ss;
}

// ---------------- launch -----------------------------------------------------

extern "C" void kernel_launch(void* const* d_in, const int* in_sizes, int n_in,
                              void* d_out, int out_size) {
    const float* x     = (const float*)d_in[0];
    const void*  ei    = d_in[1];
    const float* ew    = (const float*)d_in[2];
    const void*  batch = d_in[3];
    const float* W  = (const float*)d_in[5];
    const float* b  = (const float*)d_in[6];
    const float* W1 = (const float*)d_in[7];
    const float* b1 = (const float*)d_in[8];

    int N = in_sizes[0] / INF_;   // 50000
    int E = in_sizes[2];          // 800000

    float* out_graph = (float*)d_out;
    float* out_node  = (float*)d_out + NG * OUTF;

    int edge_blocks = ((E + 1) / 2 + 255) / 256;   // x2-unrolled edge kernels

    // fork: gemm on side stream (depends on nothing)
    cudaEventRecord(g_ss.eFork, 0);
    cudaStreamWaitEvent(g_ss.s, g_ss.eFork, 0);
    k_gemm<<<(N + 63) / 64, 256, 0, g_ss.s>>>(x, W, N);
    cudaEventRecord(g_ss.eJoin, g_ss.s);

    // main chain: prep -> deg -> scan -> fill (overlaps gemm)
    k_prep<<<(N + 255) / 256, 256>>>((const int*)ei, N);
    k_deg<<<edge_blocks, 256>>>(ei, ew, E);
    k_scan<<<(N + 255) / 256, 256>>>(batch, N);
    k_fill<<<edge_blocks, 256>>>(ei, ew, E);

    // join: aggregate needs both h (gemm) and CSR (fill)
    cudaStreamWaitEvent(0, g_ss.eJoin, 0);
    k_agg<<<(N + 7) / 8, 256>>>(b, out_node, N);
    k_pool<<<NG * 4, 256>>>(out_node, W1, b1, out_graph);
}